// round 2
// baseline (speedup 1.0000x reference)
#include <cuda_runtime.h>
#include <math.h>

#define NTOK    128
#define TSAMP   32768
#define KWIN    1024
#define WSTRIDE 512
#define NW      63
#define H       1024
#define G4      4096
#define ND      (NTOK*NW)      // 8064 decoder steps
#define NCTA    128
#define TPB     256

// -------- device-global scratch (static allocation is allowed) --------
__device__ float g_C [KWIN*KWIN];     //  4 MB  cos DFT matrix
__device__ float g_Md[G4*KWIN];       // 16 MB  Wih_d @ C
__device__ float g_Me[G4*KWIN];       // 16 MB  Wih_e @ C
__device__ float g_Gd[ND*G4];         // 132 MB precomputed decoder input gates (+b_d)
__device__ float g_Ge[NW*G4];         //  1 MB  precomputed encoder input gates (+b_e)
__device__ float g_h [H];
__device__ float g_h2[H];
__device__ unsigned g_bar;

// ---------------------------------------------------------------------
// Kernel 0: build cos matrix C[k][n] = cos(2*pi*k*n/1024), reset barrier
// ---------------------------------------------------------------------
__global__ void fill_C() {
    int idx = blockIdx.x * 256 + threadIdx.x;
    if (idx == 0) g_bar = 0u;
    int k = idx >> 10;
    int n = idx & 1023;
    int m = (k * n) & 1023;                       // exact mod -> accurate cospif
    g_C[idx] = cospif((float)m * (1.0f / 512.0f)); // cos(2*pi*m/1024)
}

// ---------------------------------------------------------------------
// Kernel 1: M = A(4096x1024) @ C(1024x1024)   (flag: 0 -> g_Md, 1 -> g_Me)
// 128x128x16 tiled fp32 SGEMM, 256 threads, 8x8 microtile
// ---------------------------------------------------------------------
__global__ __launch_bounds__(256) void gemm_nn(const float* __restrict__ A, int flag) {
    const int M = G4, N = KWIN, K = KWIN;
    float* __restrict__ D = flag ? g_Me : g_Md;
    const float* __restrict__ B = g_C;

    __shared__ float As[16][128];
    __shared__ float Bs[16][128];
    int tid = threadIdx.x;
    int tr = tid >> 4, tc = tid & 15;
    int brow = blockIdx.y, bcol = blockIdx.x;
    const float* Ab = A + (size_t)brow * 128 * K;
    const float* Bb = B + (size_t)bcol * 128;

    float acc[8][8];
#pragma unroll
    for (int i = 0; i < 8; i++)
#pragma unroll
        for (int jj = 0; jj < 8; jj++) acc[i][jj] = 0.0f;

    for (int k0 = 0; k0 < K; k0 += 16) {
#pragma unroll
        for (int p = 0; p < 2; p++) {
            int ar = (tid >> 2) + p * 64;
            int ac = (tid & 3) * 4;
            float4 v = *(const float4*)(Ab + (size_t)ar * K + k0 + ac);
            As[ac + 0][ar] = v.x; As[ac + 1][ar] = v.y;
            As[ac + 2][ar] = v.z; As[ac + 3][ar] = v.w;
        }
#pragma unroll
        for (int p = 0; p < 2; p++) {
            int br = (tid >> 5) + p * 8;
            int bc = (tid & 31) * 4;
            *(float4*)&Bs[br][bc] = *(const float4*)(Bb + (size_t)(k0 + br) * N + bc);
        }
        __syncthreads();
#pragma unroll
        for (int kk = 0; kk < 16; kk++) {
            float4 a0 = *(float4*)&As[kk][tr * 8];
            float4 a1 = *(float4*)&As[kk][tr * 8 + 4];
            float4 b0 = *(float4*)&Bs[kk][tc * 8];
            float4 b1 = *(float4*)&Bs[kk][tc * 8 + 4];
            float av[8] = {a0.x,a0.y,a0.z,a0.w,a1.x,a1.y,a1.z,a1.w};
            float bv[8] = {b0.x,b0.y,b0.z,b0.w,b1.x,b1.y,b1.z,b1.w};
#pragma unroll
            for (int i = 0; i < 8; i++)
#pragma unroll
                for (int jj = 0; jj < 8; jj++) acc[i][jj] += av[i] * bv[jj];
        }
        __syncthreads();
    }
#pragma unroll
    for (int i = 0; i < 8; i++)
#pragma unroll
        for (int jj = 0; jj < 8; jj++)
            D[(size_t)(brow * 128 + tr * 8 + i) * N + bcol * 128 + tc * 8 + jj] = acc[i][jj];
}

// ---------------------------------------------------------------------
// Kernel 2: G[t][r] = sum_n window(t,n) * M[r][n] + bias[r]
//   window(t,n) = x[t/63][ (t%63)*512 + n ]
//   flag 0: M = g_Md -> g_Gd (Mrows=8064), flag 1: M = g_Me -> g_Ge (Mrows=63)
// ---------------------------------------------------------------------
__global__ __launch_bounds__(256) void gemm_win(const float* __restrict__ x,
                                                const float* __restrict__ bias,
                                                int flag, int Mrows) {
    const float* __restrict__ W = flag ? g_Me : g_Md;   // 4096 x 1024
    float* __restrict__ D = flag ? g_Ge : g_Gd;

    __shared__ float As[16][128];
    __shared__ float Bs[16][128];
    int tid = threadIdx.x;
    int tr = tid >> 4, tc = tid & 15;
    int brow = blockIdx.y, bcol = blockIdx.x;

    float acc[8][8];
#pragma unroll
    for (int i = 0; i < 8; i++)
#pragma unroll
        for (int jj = 0; jj < 8; jj++) acc[i][jj] = 0.0f;

    for (int k0 = 0; k0 < 1024; k0 += 16) {
#pragma unroll
        for (int p = 0; p < 2; p++) {
            int ar = (tid >> 2) + p * 64;
            int ac = (tid & 3) * 4;
            int t = brow * 128 + ar;
            float4 v = make_float4(0.f, 0.f, 0.f, 0.f);
            if (t < Mrows) {
                int s = t / 63;
                int w = t - s * 63;
                v = *(const float4*)(x + (size_t)s * TSAMP + w * WSTRIDE + k0 + ac);
            }
            As[ac + 0][ar] = v.x; As[ac + 1][ar] = v.y;
            As[ac + 2][ar] = v.z; As[ac + 3][ar] = v.w;
        }
#pragma unroll
        for (int p = 0; p < 2; p++) {
            int rr = (tid >> 2) + p * 64;
            int nc = (tid & 3) * 4;
            float4 v = *(const float4*)(W + (size_t)(bcol * 128 + rr) * 1024 + k0 + nc);
            Bs[nc + 0][rr] = v.x; Bs[nc + 1][rr] = v.y;
            Bs[nc + 2][rr] = v.z; Bs[nc + 3][rr] = v.w;
        }
        __syncthreads();
#pragma unroll
        for (int kk = 0; kk < 16; kk++) {
            float4 a0 = *(float4*)&As[kk][tr * 8];
            float4 a1 = *(float4*)&As[kk][tr * 8 + 4];
            float4 b0 = *(float4*)&Bs[kk][tc * 8];
            float4 b1 = *(float4*)&Bs[kk][tc * 8 + 4];
            float av[8] = {a0.x,a0.y,a0.z,a0.w,a1.x,a1.y,a1.z,a1.w};
            float bv[8] = {b0.x,b0.y,b0.z,b0.w,b1.x,b1.y,b1.z,b1.w};
#pragma unroll
            for (int i = 0; i < 8; i++)
#pragma unroll
                for (int jj = 0; jj < 8; jj++) acc[i][jj] += av[i] * bv[jj];
        }
        __syncthreads();
    }
    int rbase = bcol * 128 + tc * 8;
    float bj[8];
#pragma unroll
    for (int jj = 0; jj < 8; jj++) bj[jj] = bias[rbase + jj];
#pragma unroll
    for (int i = 0; i < 8; i++) {
        int t = brow * 128 + tr * 8 + i;
        if (t < Mrows) {
#pragma unroll
            for (int jj = 0; jj < 8; jj++)
                D[(size_t)t * G4 + rbase + jj] = acc[i][jj] + bj[jj];
        }
    }
}

// ---------------------------------------------------------------------
// Persistent sequential kernel: encoder(63) + mid MLP + decoder(8064)
// 128 CTAs x 256 threads, 1 CTA/SM, custom monotonic grid barrier.
// warp w of CTA b owns hidden element j = b*8 + w.
// ---------------------------------------------------------------------
__device__ __forceinline__ float wredsum(float v) {
    v += __shfl_xor_sync(0xffffffffu, v, 16);
    v += __shfl_xor_sync(0xffffffffu, v, 8);
    v += __shfl_xor_sync(0xffffffffu, v, 4);
    v += __shfl_xor_sync(0xffffffffu, v, 2);
    v += __shfl_xor_sync(0xffffffffu, v, 1);
    return v;
}
__device__ __forceinline__ float sigm(float x) { return 1.0f / (1.0f + __expf(-x)); }

__device__ __forceinline__ void gridbar(unsigned ep) {
    __threadfence();
    __syncthreads();
    if (threadIdx.x == 0) {
        atomicAdd(&g_bar, 1u);
        unsigned target = ep * NCTA;
        while (*(volatile unsigned*)&g_bar < target) { }
    }
    __syncthreads();
}

__global__ __launch_bounds__(TPB, 1) void seq_kernel(
    const float* __restrict__ Whh_e,
    const float* __restrict__ Wm1, const float* __restrict__ bm1,
    const float* __restrict__ Wm2, const float* __restrict__ bm2,
    const float* __restrict__ Whh_d,
    const float* __restrict__ Wo,  const float* __restrict__ bo,
    float* __restrict__ out)
{
    __shared__ float sh[H];
    int tid  = threadIdx.x;
    int lane = tid & 31;
    int warp = tid >> 5;
    int j = blockIdx.x * 8 + warp;
    unsigned ep = 0;

    // ---- decoder recurrent weights + output weights -> registers ----
    float wr[128];
#pragma unroll
    for (int q = 0; q < 4; q++)
#pragma unroll
        for (int k = 0; k < 32; k++)
            wr[q * 32 + k] = Whh_d[(size_t)(q * H + j) * H + k * 32 + lane];
    float wo[32];
#pragma unroll
    for (int k = 0; k < 32; k++) wo[k] = Wo[(size_t)j * H + k * 32 + lane];
    float bo_j = bo[j];

    // ---- init h = 0 ----
#pragma unroll
    for (int u = 0; u < 4; u++) sh[tid + 256 * u] = 0.0f;
    __syncthreads();

    // ================= encoder (token 0 only), 63 steps =================
    float c = 0.0f;
    const float* we0 = Whh_e + (size_t)(0 * H + j) * H + lane;
    const float* we1 = Whh_e + (size_t)(1 * H + j) * H + lane;
    const float* we2 = Whh_e + (size_t)(2 * H + j) * H + lane;
    const float* we3 = Whh_e + (size_t)(3 * H + j) * H + lane;

    for (int t = 0; t < NW; t++) {
        float a0 = 0.f, a1 = 0.f, a2 = 0.f, a3 = 0.f;
#pragma unroll
        for (int k = 0; k < 32; k++) {
            float hv = sh[k * 32 + lane];
            a0 += we0[k * 32] * hv;
            a1 += we1[k * 32] * hv;
            a2 += we2[k * 32] * hv;
            a3 += we3[k * 32] * hv;
        }
        a0 = wredsum(a0); a1 = wredsum(a1); a2 = wredsum(a2); a3 = wredsum(a3);
        const float* ge = g_Ge + (size_t)t * G4;
        float iv = sigm(a0 + ge[j]);
        float fv = sigm(a1 + ge[H + j]);
        float gv = tanhf(a2 + ge[2 * H + j]);
        float ov = sigm(a3 + ge[3 * H + j]);
        c = fv * c + iv * gv;
        float hnew = ov * tanhf(c);
        if (lane == 0) g_h[j] = hnew;
        gridbar(++ep);
#pragma unroll
        for (int u = 0; u < 4; u++) sh[tid + 256 * u] = __ldcg(&g_h[tid + 256 * u]);
        __syncthreads();
    }

    // ================= mid MLP: relu(h@Wm1^T+bm1) -> tanh(.@Wm2^T+bm2) ====
    {
        float a = 0.f;
        const float* w = Wm1 + (size_t)j * H + lane;
#pragma unroll
        for (int k = 0; k < 32; k++) a += w[k * 32] * sh[k * 32 + lane];
        a = wredsum(a) + bm1[j];
        a = fmaxf(a, 0.0f);
        if (lane == 0) g_h2[j] = a;
        gridbar(++ep);
#pragma unroll
        for (int u = 0; u < 4; u++) sh[tid + 256 * u] = __ldcg(&g_h2[tid + 256 * u]);
        __syncthreads();
    }
    {
        float a = 0.f;
        const float* w = Wm2 + (size_t)j * H + lane;
#pragma unroll
        for (int k = 0; k < 32; k++) a += w[k * 32] * sh[k * 32 + lane];
        a = wredsum(a) + bm2[j];
        a = tanhf(a);
        if (lane == 0) g_h[j] = a;
        gridbar(++ep);
#pragma unroll
        for (int u = 0; u < 4; u++) sh[tid + 256 * u] = __ldcg(&g_h[tid + 256 * u]);
        __syncthreads();
    }

    // ================= decoder: 8064 steps, h0 = c0 = h_mid ==============
    c = sh[j];
    float gi = g_Gd[j], gf = g_Gd[H + j], gg = g_Gd[2 * H + j], go = g_Gd[3 * H + j];
    int wcnt = 0, tok = 0;

    for (int t = 0; t < ND; t++) {
        // prefetch next step's input gates (hidden under this step's compute)
        int tn = (t + 1 < ND) ? (t + 1) : t;
        const float* gp = g_Gd + (size_t)tn * G4;
        float ngi = gp[j], ngf = gp[H + j], ngg = gp[2 * H + j], ngo = gp[3 * H + j];

        float a0 = 0.f, a1 = 0.f, a2 = 0.f, a3 = 0.f;
#pragma unroll
        for (int k = 0; k < 32; k++) {
            float hv = sh[k * 32 + lane];
            a0 += wr[k]      * hv;
            a1 += wr[32 + k] * hv;
            a2 += wr[64 + k] * hv;
            a3 += wr[96 + k] * hv;
        }
        a0 = wredsum(a0); a1 = wredsum(a1); a2 = wredsum(a2); a3 = wredsum(a3);
        float iv = sigm(a0 + gi);
        float fv = sigm(a1 + gf);
        float gv = tanhf(a2 + gg);
        float ov = sigm(a3 + go);
        c = fv * c + iv * gv;
        float hnew = ov * tanhf(c);
        if (lane == 0) g_h[j] = hnew;
        gi = ngi; gf = ngf; gg = ngg; go = ngo;

        gridbar(++ep);
#pragma unroll
        for (int u = 0; u < 4; u++) sh[tid + 256 * u] = __ldcg(&g_h[tid + 256 * u]);
        __syncthreads();

        if (++wcnt == 63) {        // token boundary: emit raw logits
            wcnt = 0;
            float z = 0.f;
#pragma unroll
            for (int k = 0; k < 32; k++) z += wo[k] * sh[k * 32 + lane];
            z = wredsum(z);
            if (lane == 0) out[(size_t)tok * H + j] = z + bo_j;
            tok++;
        }
    }
}

// ---------------------------------------------------------------------
// Final: in-place log_softmax over each 1024-wide row of out
// ---------------------------------------------------------------------
__global__ __launch_bounds__(256) void lsm_kernel(float* __restrict__ out) {
    __shared__ float sred[8];
    int tid = threadIdx.x, lane = tid & 31, warp = tid >> 5;
    float* z = out + (size_t)blockIdx.x * H;
    float v[4];
    float m = -1e30f;
#pragma unroll
    for (int u = 0; u < 4; u++) { v[u] = z[tid + 256 * u]; m = fmaxf(m, v[u]); }
#pragma unroll
    for (int off = 16; off; off >>= 1) m = fmaxf(m, __shfl_xor_sync(0xffffffffu, m, off));
    if (lane == 0) sred[warp] = m;
    __syncthreads();
    if (tid == 0) {
        float mm = sred[0];
        for (int w = 1; w < 8; w++) mm = fmaxf(mm, sred[w]);
        sred[0] = mm;
    }
    __syncthreads();
    m = sred[0];
    __syncthreads();
    float s = 0.f;
#pragma unroll
    for (int u = 0; u < 4; u++) s += __expf(v[u] - m);
#pragma unroll
    for (int off = 16; off; off >>= 1) s += __shfl_xor_sync(0xffffffffu, s, off);
    if (lane == 0) sred[warp] = s;
    __syncthreads();
    if (tid == 0) {
        float st = 0.f;
        for (int w = 0; w < 8; w++) st += sred[w];
        sred[0] = st;
    }
    __syncthreads();
    float l = m + logf(sred[0]);
#pragma unroll
    for (int u = 0; u < 4; u++) z[tid + 256 * u] = v[u] - l;
}

// ---------------------------------------------------------------------
extern "C" void kernel_launch(void* const* d_in, const int* in_sizes, int n_in,
                              void* d_out, int out_size) {
    const float* x     = (const float*)d_in[0];
    const float* Wih_e = (const float*)d_in[1];
    const float* Whh_e = (const float*)d_in[2];
    const float* b_e   = (const float*)d_in[3];
    const float* Wm1   = (const float*)d_in[4];
    const float* bm1   = (const float*)d_in[5];
    const float* Wm2   = (const float*)d_in[6];
    const float* bm2   = (const float*)d_in[7];
    const float* Wih_d = (const float*)d_in[8];
    const float* Whh_d = (const float*)d_in[9];
    const float* b_d   = (const float*)d_in[10];
    const float* Wo    = (const float*)d_in[11];
    const float* bo    = (const float*)d_in[12];
    float* out = (float*)d_out;

    // 0) cos matrix + barrier reset
    fill_C<<<4096, 256>>>();

    // 1) fold DFT into input projections: M = Wih @ C
    dim3 gnn(KWIN / 128, G4 / 128);   // (8, 32)
    gemm_nn<<<gnn, 256>>>(Wih_d, 0);  // -> g_Md
    gemm_nn<<<gnn, 256>>>(Wih_e, 1);  // -> g_Me

    // 2) precompute all input gates:  G = windows @ M^T + b
    gemm_win<<<dim3(G4 / 128, ND / 128), 256>>>(x, b_d, 0, ND);  // -> g_Gd (8064x4096)
    gemm_win<<<dim3(G4 / 128, 1),        256>>>(x, b_e, 1, NW);  // -> g_Ge (63x4096)

    // 3) sequential encoder + MLP + decoder (persistent, grid-barriered)
    seq_kernel<<<NCTA, TPB>>>(Whh_e, Wm1, bm1, Wm2, bm2, Whh_d, Wo, bo, out);

    // 4) log_softmax per token row
    lsm_kernel<<<NTOK, 256>>>(out);
}